// round 15
// baseline (speedup 1.0000x reference)
#include <cuda_runtime.h>

typedef unsigned long long ull;

#define HID   128
#define TT    512
#define NB    2048
#define RPC   8
#define NCTA  (NB / RPC)   // 256
#define NTHR  256

// Blocked weights: [kq][gate*128+j][k%4] -> 16B load at (kq,g,j) = W[g,j][4 consecutive k]
// 0: Wh0, 1: Wi1, 2: Wh1
__device__ __align__(16) float g_wt[3][128 * 384];

__global__ void transpose_k(const float* __restrict__ Wh0,
                            const float* __restrict__ Wi1,
                            const float* __restrict__ Wh1) {
    int idx = blockIdx.x * blockDim.x + threadIdx.x;
    if (idx >= 128 * 384) return;
    int kq  = idx / 1536;
    int rem = idx - kq * 1536;
    int gj  = rem >> 2;
    int k   = kq * 4 + (rem & 3);
    g_wt[0][idx] = Wh0[gj * HID + k];
    g_wt[1][idx] = Wi1[gj * HID + k];
    g_wt[2][idx] = Wh1[gj * HID + k];
}

// ---- packed f32x2 helpers ----
__device__ __forceinline__ void ffma2(ull& d, ull a, ull b) {
    asm("fma.rn.f32x2 %0, %1, %2, %0;" : "+l"(d) : "l"(a), "l"(b));
}
__device__ __forceinline__ float hadd2(ull v) {
    float lo, hi; asm("mov.b64 {%0, %1}, %2;" : "=f"(lo), "=f"(hi) : "l"(v)); return lo + hi;
}
__device__ __forceinline__ float tanhap(float x) {
    float y; asm("tanh.approx.f32 %0, %1;" : "=f"(y) : "f"(x)); return y;
}
__device__ __forceinline__ float sigap(float x) {
    return fmaf(tanhap(0.5f * x), 0.5f, 0.5f);
}

__global__ void __launch_bounds__(NTHR, 2)
gru_kernel(const float* __restrict__ x,
           const float* __restrict__ noise_z,
           const float* __restrict__ context,
           const float* __restrict__ Wi0,
           const float* __restrict__ bi0,
           const float* __restrict__ bh0,
           const float* __restrict__ bi1,
           const float* __restrict__ bh1,
           const float* __restrict__ Wa,
           const float* __restrict__ ba,
           float* __restrict__ out) {
    __shared__ __align__(16) float h0s[2][RPC][128];   // [buf][r][k]
    __shared__ __align__(16) float h1s[2][RPC][128];
    __shared__ __align__(16) float ctxgi[3][RPC][128]; // [g][r][j]
    __shared__ __align__(16) float was[256];           // Wa staged
    __shared__ __align__(16) float decs[2][RPC];       // feedback [s][r]

    const int tid = threadIdx.x;
    const int hf  = tid >> 7;          // row-half
    const int j   = tid & 127;         // output neuron
    const int r0  = hf * 4;            // 4 rows per thread
    const int brow0 = blockIdx.x * RPC;

    // ---- init ----
    for (int i = tid; i < 2 * RPC * 128; i += NTHR) {
        (&h0s[0][0][0])[i] = 0.f;
        (&h1s[0][0][0])[i] = 0.f;
    }
    was[tid] = Wa[tid];
    if (tid < 2 * RPC) {
        int r = tid >> 1, s = tid & 1;
        decs[s][r] = noise_z[(brow0 + r) * 2 + s];
    }

    // per-thread constants
    const float bh0r = bh0[j], bh0z = bh0[128 + j], bh0n = bh0[256 + j];
    const float brzr = bi1[j] + bh1[j];
    const float brzz = bi1[128 + j] + bh1[128 + j];
    const float binn = bi1[256 + j];
    const float bhnn = bh1[256 + j];
    float wd0[3], wd1[3];
#pragma unroll
    for (int g = 0; g < 3; ++g) {
        wd0[g] = Wi0[(g * 128 + j) * 12 + 0];
        wd1[g] = Wi0[(g * 128 + j) * 12 + 1];
    }

    // ctx gates: bi0 + context-part (time invariant)
#pragma unroll
    for (int g = 0; g < 3; ++g) {
        int gj = g * 128 + j;
        float wrow[10];
#pragma unroll
        for (int e = 0; e < 10; ++e) wrow[e] = Wi0[gj * 12 + 2 + e];
        float b = bi0[gj];
        for (int q = 0; q < 4; ++q) {
            int r = r0 + q;
            float acc = b;
#pragma unroll
            for (int e = 0; e < 10; ++e) acc += context[(brow0 + r) * 10 + e] * wrow[e];
            ctxgi[g][r][j] = acc;
        }
    }

    // head role (ALL 256 threads): 16 outputs x 16 lanes of 8 k each
    const int hr = (tid >> 5) & 7;     // row 0..7
    const int hs = (tid >> 4) & 1;     // state 0/1
    const int hl = tid & 15;           // k-slice 0..15 (8 floats each)
    const float bas = ba[hs];

    const ulonglong2* w0b = reinterpret_cast<const ulonglong2*>(g_wt[0]) + j;
    const ulonglong2* wib = reinterpret_cast<const ulonglong2*>(g_wt[1]) + j;
    const ulonglong2* whb = reinterpret_cast<const ulonglong2*>(g_wt[2]) + j;

    __syncthreads();

    int p = 0;
    for (int t = -1; t < TT; ++t) {
        // ================= layer 0: gh0 = h0_old @ Wh0^T =================
        ull A0[4], A1[4], A2[4];
#pragma unroll
        for (int rr = 0; rr < 4; ++rr) { A0[rr] = 0ull; A1[rr] = 0ull; A2[rr] = 0ull; }
        {
            const float (*hb)[128] = h0s[p];
#pragma unroll 4
            for (int kq = 0; kq < 32; ++kq) {
                ulonglong2 wA = w0b[kq * 384];
                ulonglong2 wB = w0b[kq * 384 + 128];
                ulonglong2 wC = w0b[kq * 384 + 256];
#pragma unroll
                for (int rr = 0; rr < 4; ++rr) {
                    ulonglong2 h = *reinterpret_cast<const ulonglong2*>(&hb[r0 + rr][kq * 4]);
                    ffma2(A0[rr], wA.x, h.x); ffma2(A0[rr], wA.y, h.y);
                    ffma2(A1[rr], wB.x, h.x); ffma2(A1[rr], wB.y, h.y);
                    ffma2(A2[rr], wC.x, h.x); ffma2(A2[rr], wC.y, h.y);
                }
            }
        }

        // layer-0 epilogue: 4 rows (decs was ordered by BAR3 of previous step)
#pragma unroll
        for (int rr = 0; rr < 4; ++rr) {
            int r = r0 + rr;
            float d0 = decs[0][r], d1 = decs[1][r];
            float rg = sigap(ctxgi[0][r][j] + d0 * wd0[0] + d1 * wd1[0] + hadd2(A0[rr]) + bh0r);
            float zg = sigap(ctxgi[1][r][j] + d0 * wd0[1] + d1 * wd1[1] + hadd2(A1[rr]) + bh0z);
            float ng = tanhap(ctxgi[2][r][j] + d0 * wd0[2] + d1 * wd1[2] +
                              rg * (hadd2(A2[rr]) + bh0n));
            float ho = h0s[p][r][j];
            h0s[p ^ 1][r][j] = ng + zg * (ho - ng);
        }
        __syncthreads();   // BAR1: new h0 visible

        // ====== layer 1: gi1 (r/z fused with gh1); n split ======
        ull Z0[4], Z1[4], Ni[4], Nh[4];
#pragma unroll
        for (int rr = 0; rr < 4; ++rr) { Z0[rr] = 0ull; Z1[rr] = 0ull; Ni[rr] = 0ull; Nh[rr] = 0ull; }
        {
            const float (*ha)[128] = h0s[p ^ 1];
            const float (*hb)[128] = h1s[p];
#pragma unroll 2
            for (int kq = 0; kq < 32; ++kq) {
                ulonglong2 U0 = wib[kq * 384];
                ulonglong2 U1 = wib[kq * 384 + 128];
                ulonglong2 U2 = wib[kq * 384 + 256];
                ulonglong2 V0 = whb[kq * 384];
                ulonglong2 V1 = whb[kq * 384 + 128];
                ulonglong2 V2 = whb[kq * 384 + 256];
#pragma unroll
                for (int rr = 0; rr < 4; ++rr) {
                    ulonglong2 a = *reinterpret_cast<const ulonglong2*>(&ha[rr + r0][kq * 4]);
                    ulonglong2 b = *reinterpret_cast<const ulonglong2*>(&hb[rr + r0][kq * 4]);
                    ffma2(Z0[rr], U0.x, a.x); ffma2(Z0[rr], U0.y, a.y);
                    ffma2(Z0[rr], V0.x, b.x); ffma2(Z0[rr], V0.y, b.y);
                    ffma2(Z1[rr], U1.x, a.x); ffma2(Z1[rr], U1.y, a.y);
                    ffma2(Z1[rr], V1.x, b.x); ffma2(Z1[rr], V1.y, b.y);
                    ffma2(Ni[rr], U2.x, a.x); ffma2(Ni[rr], U2.y, a.y);
                    ffma2(Nh[rr], V2.x, b.x); ffma2(Nh[rr], V2.y, b.y);
                }
            }
        }

        // layer-1 epilogue
#pragma unroll
        for (int rr = 0; rr < 4; ++rr) {
            int r = r0 + rr;
            float rg = sigap(hadd2(Z0[rr]) + brzr);
            float zg = sigap(hadd2(Z1[rr]) + brzz);
            float ng = tanhap(hadd2(Ni[rr]) + binn + rg * (hadd2(Nh[rr]) + bhnn));
            float ho = h1s[p][r][j];
            h1s[p ^ 1][r][j] = ng + zg * (ho - ng);
        }
        __syncthreads();   // BAR2: new h1 visible

        // ========== output head (ALL 256 threads) + autoregressive feedback ==========
        if (t >= 0) {
            ull acc = 0ull;
            const float* hrow = &h1s[p ^ 1][hr][hl * 8];
            const float* wrow = &was[hs * 128 + hl * 8];
            {
                ulonglong2 hv0 = *reinterpret_cast<const ulonglong2*>(&hrow[0]);
                ulonglong2 wv0 = *reinterpret_cast<const ulonglong2*>(&wrow[0]);
                ulonglong2 hv1 = *reinterpret_cast<const ulonglong2*>(&hrow[4]);
                ulonglong2 wv1 = *reinterpret_cast<const ulonglong2*>(&wrow[4]);
                ffma2(acc, wv0.x, hv0.x);
                ffma2(acc, wv0.y, hv0.y);
                ffma2(acc, wv1.x, hv1.x);
                ffma2(acc, wv1.y, hv1.y);
            }
            float v = hadd2(acc);
            v += __shfl_xor_sync(0xffffffffu, v, 1, 16);
            v += __shfl_xor_sync(0xffffffffu, v, 2, 16);
            v += __shfl_xor_sync(0xffffffffu, v, 4, 16);
            v += __shfl_xor_sync(0xffffffffu, v, 8, 16);
            if (hl == 0) {
                float o = v + bas;
                decs[hs][hr] = o;
                out[(size_t)(brow0 + hr) * (TT * 2) + t * 2 + hs] = o;
            }
        } else {
            if (tid < 2 * RPC) {
                int r = tid >> 1, s = tid & 1;
                decs[s][r] = x[(size_t)(brow0 + r) * (TT * 2) + s];
            }
        }
        __syncthreads();   // BAR3: decs visible for next step's layer-0 epilogue
        p ^= 1;
    }
}

extern "C" void kernel_launch(void* const* d_in, const int* in_sizes, int n_in,
                              void* d_out, int out_size) {
    const float* x       = (const float*)d_in[0];
    const float* noise_z = (const float*)d_in[1];
    const float* context = (const float*)d_in[2];
    const float* Wi0     = (const float*)d_in[3];
    const float* Wh0     = (const float*)d_in[4];
    const float* bi0     = (const float*)d_in[5];
    const float* bh0     = (const float*)d_in[6];
    const float* Wi1     = (const float*)d_in[7];
    const float* Wh1     = (const float*)d_in[8];
    const float* bi1     = (const float*)d_in[9];
    const float* bh1     = (const float*)d_in[10];
    const float* Wa      = (const float*)d_in[11];
    const float* ba      = (const float*)d_in[12];
    float* out = (float*)d_out;

    transpose_k<<<192, 256>>>(Wh0, Wi1, Wh1);
    gru_kernel<<<NCTA, NTHR>>>(x, noise_z, context, Wi0, bi0, bh0,
                               bi1, bh1, Wa, ba, out);
}

// round 16
// speedup vs baseline: 1.0063x; 1.0063x over previous
#include <cuda_runtime.h>

typedef unsigned long long ull;

#define HID   128
#define TT    512
#define NB    2048
#define RPC   8
#define NCTA  (NB / RPC)   // 256
#define NTHR  256

// Blocked weights: [kq][gate*128+j][k%4] -> 16B load at (kq,g,j) = W[g,j][4 consecutive k]
// 0: Wh0, 1: Wi1, 2: Wh1
__device__ __align__(16) float g_wt[3][128 * 384];

__global__ void transpose_k(const float* __restrict__ Wh0,
                            const float* __restrict__ Wi1,
                            const float* __restrict__ Wh1) {
    int idx = blockIdx.x * blockDim.x + threadIdx.x;
    if (idx >= 128 * 384) return;
    int kq  = idx / 1536;
    int rem = idx - kq * 1536;
    int gj  = rem >> 2;
    int k   = kq * 4 + (rem & 3);
    g_wt[0][idx] = Wh0[gj * HID + k];
    g_wt[1][idx] = Wi1[gj * HID + k];
    g_wt[2][idx] = Wh1[gj * HID + k];
}

// ---- packed f32x2 helpers ----
__device__ __forceinline__ void ffma2(ull& d, ull a, ull b) {
    asm("fma.rn.f32x2 %0, %1, %2, %0;" : "+l"(d) : "l"(a), "l"(b));
}
__device__ __forceinline__ float hadd2(ull v) {
    float lo, hi; asm("mov.b64 {%0, %1}, %2;" : "=f"(lo), "=f"(hi) : "l"(v)); return lo + hi;
}
__device__ __forceinline__ float tanhap(float x) {
    float y; asm("tanh.approx.f32 %0, %1;" : "=f"(y) : "f"(x)); return y;
}
__device__ __forceinline__ float sigap(float x) {
    return fmaf(tanhap(0.5f * x), 0.5f, 0.5f);
}

__global__ void __launch_bounds__(NTHR, 2)
gru_kernel(const float* __restrict__ x,
           const float* __restrict__ noise_z,
           const float* __restrict__ context,
           const float* __restrict__ Wi0,
           const float* __restrict__ bi0,
           const float* __restrict__ bh0,
           const float* __restrict__ bi1,
           const float* __restrict__ bh1,
           const float* __restrict__ Wa,
           const float* __restrict__ ba,
           float* __restrict__ out) {
    __shared__ __align__(16) float h0s[2][RPC][128];   // [buf][r][k]
    __shared__ __align__(16) float h1s[2][RPC][128];
    __shared__ __align__(16) float ctxgi[3][RPC][128]; // [g][r][j]
    __shared__ __align__(16) float was[256];           // Wa staged
    __shared__ __align__(16) float decs[2][RPC];       // feedback [s][r]

    const int tid = threadIdx.x;
    const int hf  = tid >> 7;          // row-half
    const int j   = tid & 127;         // output neuron
    const int r0  = hf * 4;            // 4 rows per thread
    const int brow0 = blockIdx.x * RPC;

    // ---- init ----
    for (int i = tid; i < 2 * RPC * 128; i += NTHR) {
        (&h0s[0][0][0])[i] = 0.f;
        (&h1s[0][0][0])[i] = 0.f;
    }
    was[tid] = Wa[tid];
    if (tid < 2 * RPC) {
        int r = tid >> 1, s = tid & 1;
        decs[s][r] = noise_z[(brow0 + r) * 2 + s];
    }

    // per-thread constants
    const float bh0r = bh0[j], bh0z = bh0[128 + j], bh0n = bh0[256 + j];
    const float brzr = bi1[j] + bh1[j];
    const float brzz = bi1[128 + j] + bh1[128 + j];
    const float binn = bi1[256 + j];
    const float bhnn = bh1[256 + j];
    float wd0[3], wd1[3];
#pragma unroll
    for (int g = 0; g < 3; ++g) {
        wd0[g] = Wi0[(g * 128 + j) * 12 + 0];
        wd1[g] = Wi0[(g * 128 + j) * 12 + 1];
    }

    // ctx gates: bi0 + context-part (time invariant)
#pragma unroll
    for (int g = 0; g < 3; ++g) {
        int gj = g * 128 + j;
        float wrow[10];
#pragma unroll
        for (int e = 0; e < 10; ++e) wrow[e] = Wi0[gj * 12 + 2 + e];
        float b = bi0[gj];
        for (int q = 0; q < 4; ++q) {
            int r = r0 + q;
            float acc = b;
#pragma unroll
            for (int e = 0; e < 10; ++e) acc += context[(brow0 + r) * 10 + e] * wrow[e];
            ctxgi[g][r][j] = acc;
        }
    }

    // head role (ALL 256 threads): 16 outputs x 16 lanes of 8 k each
    const int hr = (tid >> 5) & 7;     // row 0..7
    const int hs = (tid >> 4) & 1;     // state 0/1
    const int hl = tid & 15;           // k-slice 0..15 (8 floats each)
    const float bas = ba[hs];

    const ulonglong2* w0b = reinterpret_cast<const ulonglong2*>(g_wt[0]) + j;
    const ulonglong2* wib = reinterpret_cast<const ulonglong2*>(g_wt[1]) + j;
    const ulonglong2* whb = reinterpret_cast<const ulonglong2*>(g_wt[2]) + j;

    __syncthreads();

    int p = 0;
    for (int t = -1; t < TT; ++t) {
        // ================= phase A1: gh0 = h0_old @ Wh0^T =================
        ull A0[4], A1[4], A2[4];
#pragma unroll
        for (int rr = 0; rr < 4; ++rr) { A0[rr] = 0ull; A1[rr] = 0ull; A2[rr] = 0ull; }
        {
            const float (*hb)[128] = h0s[p];
#pragma unroll 4
            for (int kq = 0; kq < 32; ++kq) {
                ulonglong2 wA = w0b[kq * 384];
                ulonglong2 wB = w0b[kq * 384 + 128];
                ulonglong2 wC = w0b[kq * 384 + 256];
#pragma unroll
                for (int rr = 0; rr < 4; ++rr) {
                    ulonglong2 h = *reinterpret_cast<const ulonglong2*>(&hb[r0 + rr][kq * 4]);
                    ffma2(A0[rr], wA.x, h.x); ffma2(A0[rr], wA.y, h.y);
                    ffma2(A1[rr], wB.x, h.x); ffma2(A1[rr], wB.y, h.y);
                    ffma2(A2[rr], wC.x, h.x); ffma2(A2[rr], wC.y, h.y);
                }
            }
        }

        // ========== phase A2 (hoisted): Vh1 @ h1_old — independent of h0_new ==========
        // h1s[p] was finalized at the previous step's BAR2; epi1 this step writes
        // only h1s[p^1], so reading h1s[p] here (before BAR1) is race-free.
        ull Z0[4], Z1[4], Nh[4];
#pragma unroll
        for (int rr = 0; rr < 4; ++rr) { Z0[rr] = 0ull; Z1[rr] = 0ull; Nh[rr] = 0ull; }
        {
            const float (*hb)[128] = h1s[p];
#pragma unroll 4
            for (int kq = 0; kq < 32; ++kq) {
                ulonglong2 V0 = whb[kq * 384];
                ulonglong2 V1 = whb[kq * 384 + 128];
                ulonglong2 V2 = whb[kq * 384 + 256];
#pragma unroll
                for (int rr = 0; rr < 4; ++rr) {
                    ulonglong2 b = *reinterpret_cast<const ulonglong2*>(&hb[rr + r0][kq * 4]);
                    ffma2(Z0[rr], V0.x, b.x); ffma2(Z0[rr], V0.y, b.y);
                    ffma2(Z1[rr], V1.x, b.x); ffma2(Z1[rr], V1.y, b.y);
                    ffma2(Nh[rr], V2.x, b.x); ffma2(Nh[rr], V2.y, b.y);
                }
            }
        }

        // layer-0 epilogue: 4 rows (decs ordered by BAR3 of previous step)
#pragma unroll
        for (int rr = 0; rr < 4; ++rr) {
            int r = r0 + rr;
            float d0 = decs[0][r], d1 = decs[1][r];
            float rg = sigap(ctxgi[0][r][j] + d0 * wd0[0] + d1 * wd1[0] + hadd2(A0[rr]) + bh0r);
            float zg = sigap(ctxgi[1][r][j] + d0 * wd0[1] + d1 * wd1[1] + hadd2(A1[rr]) + bh0z);
            float ng = tanhap(ctxgi[2][r][j] + d0 * wd0[2] + d1 * wd1[2] +
                              rg * (hadd2(A2[rr]) + bh0n));
            float ho = h0s[p][r][j];
            h0s[p ^ 1][r][j] = ng + zg * (ho - ng);
        }
        __syncthreads();   // BAR1: new h0 visible

        // ========== phase B: Ui1 @ h0_new (adds into Z0/Z1; Ni fresh) ==========
        ull Ni[4];
#pragma unroll
        for (int rr = 0; rr < 4; ++rr) Ni[rr] = 0ull;
        {
            const float (*ha)[128] = h0s[p ^ 1];
#pragma unroll 4
            for (int kq = 0; kq < 32; ++kq) {
                ulonglong2 U0 = wib[kq * 384];
                ulonglong2 U1 = wib[kq * 384 + 128];
                ulonglong2 U2 = wib[kq * 384 + 256];
#pragma unroll
                for (int rr = 0; rr < 4; ++rr) {
                    ulonglong2 a = *reinterpret_cast<const ulonglong2*>(&ha[rr + r0][kq * 4]);
                    ffma2(Z0[rr], U0.x, a.x); ffma2(Z0[rr], U0.y, a.y);
                    ffma2(Z1[rr], U1.x, a.x); ffma2(Z1[rr], U1.y, a.y);
                    ffma2(Ni[rr], U2.x, a.x); ffma2(Ni[rr], U2.y, a.y);
                }
            }
        }

        // layer-1 epilogue
#pragma unroll
        for (int rr = 0; rr < 4; ++rr) {
            int r = r0 + rr;
            float rg = sigap(hadd2(Z0[rr]) + brzr);
            float zg = sigap(hadd2(Z1[rr]) + brzz);
            float ng = tanhap(hadd2(Ni[rr]) + binn + rg * (hadd2(Nh[rr]) + bhnn));
            float ho = h1s[p][r][j];
            h1s[p ^ 1][r][j] = ng + zg * (ho - ng);
        }
        __syncthreads();   // BAR2: new h1 visible

        // ========== output head (ALL 256 threads) + autoregressive feedback ==========
        if (t >= 0) {
            ull acc = 0ull;
            const float* hrow = &h1s[p ^ 1][hr][hl * 8];
            const float* wrow = &was[hs * 128 + hl * 8];
            {
                ulonglong2 hv0 = *reinterpret_cast<const ulonglong2*>(&hrow[0]);
                ulonglong2 wv0 = *reinterpret_cast<const ulonglong2*>(&wrow[0]);
                ulonglong2 hv1 = *reinterpret_cast<const ulonglong2*>(&hrow[4]);
                ulonglong2 wv1 = *reinterpret_cast<const ulonglong2*>(&wrow[4]);
                ffma2(acc, wv0.x, hv0.x);
                ffma2(acc, wv0.y, hv0.y);
                ffma2(acc, wv1.x, hv1.x);
                ffma2(acc, wv1.y, hv1.y);
            }
            float v = hadd2(acc);
            v += __shfl_xor_sync(0xffffffffu, v, 1, 16);
            v += __shfl_xor_sync(0xffffffffu, v, 2, 16);
            v += __shfl_xor_sync(0xffffffffu, v, 4, 16);
            v += __shfl_xor_sync(0xffffffffu, v, 8, 16);
            if (hl == 0) {
                float o = v + bas;
                decs[hs][hr] = o;
                out[(size_t)(brow0 + hr) * (TT * 2) + t * 2 + hs] = o;
            }
        } else {
            if (tid < 2 * RPC) {
                int r = tid >> 1, s = tid & 1;
                decs[s][r] = x[(size_t)(brow0 + r) * (TT * 2) + s];
            }
        }
        __syncthreads();   // BAR3: decs visible for next step's layer-0 epilogue
        p ^= 1;
    }
}

extern "C" void kernel_launch(void* const* d_in, const int* in_sizes, int n_in,
                              void* d_out, int out_size) {
    const float* x       = (const float*)d_in[0];
    const float* noise_z = (const float*)d_in[1];
    const float* context = (const float*)d_in[2];
    const float* Wi0     = (const float*)d_in[3];
    const float* Wh0     = (const float*)d_in[4];
    const float* bi0     = (const float*)d_in[5];
    const float* bh0     = (const float*)d_in[6];
    const float* Wi1     = (const float*)d_in[7];
    const float* Wh1     = (const float*)d_in[8];
    const float* bi1     = (const float*)d_in[9];
    const float* bh1     = (const float*)d_in[10];
    const float* Wa      = (const float*)d_in[11];
    const float* ba      = (const float*)d_in[12];
    float* out = (float*)d_out;

    transpose_k<<<192, 256>>>(Wh0, Wi1, Wh1);
    gru_kernel<<<NCTA, NTHR>>>(x, noise_z, context, Wi0, bi0, bh0,
                               bi1, bh1, Wa, ba, out);
}